// round 8
// baseline (speedup 1.0000x reference)
#include <cuda_runtime.h>

#define BATCH   64
#define TSTEPS  1024
#define DIM     512
#define NCTA    128          // 8 b-groups x 16 j-groups; co-resident on 148 SMs
#define NBG     8            // b-groups
#define NJG     16           // j-groups per b-group

#define HSTRIDE 576          // staged row stride: 16 chunks x (32 data + 4 pad)
#define PROW    33           // part row stride (floats)
#define PSEG    (8 * PROW)   // part segment stride (264 floats)

// ---------------- scratch (device globals; no allocations) ------------------
__device__ float    g_h[2][BATCH * DIM];          // ping-pong hidden state
__device__ unsigned g_flag[TSTEPS * NBG * NJG];   // h_t tile-ready flags (512KB)

// ---------------- f32x2 packed-FMA helpers (sm_100+ PTX) --------------------
static __device__ __forceinline__ unsigned long long packf2(float lo, float hi) {
    unsigned long long r;
    asm("mov.b64 %0, {%1, %2};" : "=l"(r) : "f"(lo), "f"(hi));
    return r;
}
static __device__ __forceinline__ void unpackf2(unsigned long long v, float& lo, float& hi) {
    asm("mov.b64 {%0, %1}, %2;" : "=f"(lo), "=f"(hi) : "l"(v));
}
static __device__ __forceinline__ unsigned long long fma2(
    unsigned long long a, unsigned long long b, unsigned long long c) {
    unsigned long long d;
    asm("fma.rn.f32x2 %0, %1, %2, %3;" : "=l"(d) : "l"(a), "l"(b), "l"(c));
    return d;
}

// Padded staged-tile address: logical (row, float4-chunk c4) -> float offset.
// Every 32-float chunk ch sits at 36*ch -> warp's two k-halves are 144B apart
// -> disjoint bank quads -> LDS.128 conflict-free.
static __device__ __forceinline__ int sw_off(int row, int c4) {
    return row * HSTRIDE + c4 * 4 + (c4 >> 3) * 4;
}

// ---------------------------------------------------------------------------
// Matmul partials: thread = (warp w: k-slice 64) x (cg: col pair) x (ks: k half)
// 8 rows x 2 cols over 32 k; writes part[seg][row][col].
// Per warp: 64 LDS.128 (conflict-free) + 256 fma2.
// ---------------------------------------------------------------------------
static __device__ __forceinline__ void mm_partials(
    const float* __restrict__ sm, const unsigned long long w2[2][16],
    int smoff, int seg, int cg, float* __restrict__ part)
{
    unsigned long long acc[8][2];
#pragma unroll
    for (int r = 0; r < 8; r++) { acc[r][0] = 0ULL; acc[r][1] = 0ULL; }

#pragma unroll
    for (int m = 0; m < 8; m++) {
#pragma unroll
        for (int r = 0; r < 8; r++) {
            ulonglong2 h2 = *(const ulonglong2*)(sm + r * HSTRIDE + smoff + m * 4);
            acc[r][0] = fma2(h2.x, w2[0][2 * m + 0], acc[r][0]);
            acc[r][0] = fma2(h2.y, w2[0][2 * m + 1], acc[r][0]);
            acc[r][1] = fma2(h2.x, w2[1][2 * m + 0], acc[r][1]);
            acc[r][1] = fma2(h2.y, w2[1][2 * m + 1], acc[r][1]);
        }
    }
#pragma unroll
    for (int r = 0; r < 8; r++) {
#pragma unroll
        for (int c = 0; c < 2; c++) {
            float lo, hi;
            unpackf2(acc[r][c], lo, hi);
            part[seg * PSEG + r * PROW + cg * 2 + c] = lo + hi;
        }
    }
}

// ---------------------------------------------------------------------------
// Fused persistent kernel: h_{t+1} = tanh( (x_t@W + b) + h_t@Wr )
// CTA c: rows [b0,b0+8), cols [j0,j0+32).
// Sync: per-producer data-ready flags. Producer: st.cg tile -> bar ->
// st.release flag. Consumer warps poll their 2 chunk flags (ld.acquire) and
// stage each 1KB chunk as it lands. Gemm for t+1 fills the flag->poll window.
// ---------------------------------------------------------------------------
__global__ void __launch_bounds__(256, 1) rnn_fused_kernel(
    const float* __restrict__ W,      // [512,512] row-major
    const float* __restrict__ Wr,     // [512,512] row-major
    const float* __restrict__ x,      // [64,1024,512]
    const float* __restrict__ bias,   // [512]
    float* __restrict__ out)          // [64,512]
{
    __shared__ float hs[8 * HSTRIDE];        // staged h tile (padded)  18 KB
    __shared__ float xs[8 * HSTRIDE];        // staged x tile (padded)  18 KB
    __shared__ float part[16 * PSEG];        // partials [16][8][33]    16.5 KB

    const int tid  = threadIdx.x;
    const int w    = tid >> 5;               // warp: k-slice [w*64, +64)
    const int lane = tid & 31;
    const int cg   = lane >> 1;              // col pair: cols j0 + cg*2 + {0,1}
    const int ks   = lane & 1;               // k half within slice
    const int c    = blockIdx.x;
    const int bg   = c >> 4;
    const int jg   = c & 15;
    const int b0   = bg * 8;
    const int j0   = jg * 32;

    const int kb    = w * 64 + ks * 32;      // logical k base
    const int smoff = w * 72 + ks * 36;      // padded smem base (chunk 2w+ks)
    const int seg   = w * 2 + ks;

    // persistent packed weights: (k, k+1) pairs for this thread's 2 columns
    unsigned long long wr2[2][16], wx2[2][16];
#pragma unroll
    for (int cc = 0; cc < 2; cc++) {
        const int j = j0 + cg * 2 + cc;
#pragma unroll
        for (int p = 0; p < 16; p++) {
            const int k = kb + 2 * p;
            wr2[cc][p] = packf2(Wr[(size_t)k * DIM + j], Wr[(size_t)(k + 1) * DIM + j]);
            wx2[cc][p] = packf2(W[(size_t)k * DIM + j],  W[(size_t)(k + 1) * DIM + j]);
        }
    }
    const int   rrow = tid >> 5;             // reduce/output row
    const int   rcol = tid & 31;             // reduce/output col
    const float bv   = bias[j0 + rcol];

    // staging mapping for warp-chunk loads: f4 index v -> (row, c4-within-chunk)
    const int sr0 = lane >> 3,  sc0 = lane & 7;          // v = lane
    const int sr1 = (lane + 32) >> 3, sc1 = (lane + 32) & 7;  // v = lane+32

    // ---- prologue: xw for t=0 ----
#pragma unroll
    for (int q = 0; q < 4; q++) {
        int idx = tid + q * 256, row = idx >> 7, c4 = idx & 127;
        *(float4*)&xs[sw_off(row, c4)] =
            __ldg((const float4*)(x + ((size_t)(b0 + row) * TSTEPS + 0) * DIM) + c4);
    }
    __syncthreads();
    mm_partials(xs, wx2, smoff, seg, cg, part);
    __syncthreads();
    float xw_cur = bv;
#pragma unroll
    for (int s8 = 0; s8 < 16; s8++) xw_cur += part[s8 * PSEG + rrow * PROW + rcol];

    for (int t = 0; t < TSTEPS; t++) {
        // ---- prefetch x[t+1] into regs (consumed after mm_r) ----
        float4 xt[4];
        const int tn = (t + 1 < TSTEPS) ? (t + 1) : (TSTEPS - 1);
#pragma unroll
        for (int q = 0; q < 4; q++) {
            int idx = tid + q * 256, row = idx >> 7, c4 = idx & 127;
            xt[q] = __ldg((const float4*)(
                x + ((size_t)(b0 + row) * TSTEPS + tn) * DIM) + c4);
        }

        // ---- stage h_t: warp w handles chunks 2w, 2w+1 (poll flag, then copy)
        {
            const float* hbuf = g_h[t & 1];
#pragma unroll
            for (int pc = 0; pc < 2; pc++) {
                const int p = w * 2 + pc;               // producer j-group
                if (t > 0) {
                    const unsigned* f = &g_flag[((unsigned)t * NBG + bg) * NJG + p];
                    unsigned v;
                    do {
                        asm volatile("ld.acquire.gpu.global.u32 %0, [%1];"
                                     : "=r"(v) : "l"(f) : "memory");
                    } while (v == 0u);
                }
                // 64 float4 per chunk: lane does v=lane and v=lane+32
                float4 d0 = __ldcg((const float4*)(hbuf + (b0 + sr0) * DIM + p * 32) + sc0);
                float4 d1 = __ldcg((const float4*)(hbuf + (b0 + sr1) * DIM + p * 32) + sc1);
                *(float4*)&hs[sr0 * HSTRIDE + p * 36 + sc0 * 4] = d0;
                *(float4*)&hs[sr1 * HSTRIDE + p * 36 + sc1 * 4] = d1;
            }
        }
        __syncthreads();                     // S1: hs complete

        // ---- recurrence: h_t @ Wr ----
        mm_partials(hs, wr2, smoff, seg, cg, part);
        __syncthreads();                     // S2: part complete (also guards hs)

        // ---- reduce + tanh + store h tile ----
        float s = xw_cur;
#pragma unroll
        for (int s8 = 0; s8 < 16; s8++) s += part[s8 * PSEG + rrow * PROW + rcol];
        float hv = tanhf(s);
        if (t == TSTEPS - 1) {
            out[(b0 + rrow) * DIM + j0 + rcol] = hv;
            return;
        }
        __stcg(&g_h[(t + 1) & 1][(b0 + rrow) * DIM + j0 + rcol], hv);
        __syncthreads();                     // S4: all tile stores issued, part read

        // ---- publish: one release-flag for this CTA's tile ----
        if (tid == 0) {
            unsigned* f = &g_flag[((unsigned)(t + 1) * NBG + bg) * NJG + jg];
            asm volatile("st.release.gpu.global.u32 [%0], %1;"
                         :: "l"(f), "r"(1u) : "memory");
        }

        // ---- gemm for t+1 fills the publish->poll window ----
#pragma unroll
        for (int q = 0; q < 4; q++) {
            int idx = tid + q * 256, row = idx >> 7, c4 = idx & 127;
            *(float4*)&xs[sw_off(row, c4)] = xt[q];
        }
        __syncthreads();                     // S5: xs complete
        mm_partials(xs, wx2, smoff, seg, cg, part);
        __syncthreads();                     // S6: part complete
        float s2 = bv;
#pragma unroll
        for (int s8 = 0; s8 < 16; s8++) s2 += part[s8 * PSEG + rrow * PROW + rcol];
        xw_cur = s2;
        // (part is not rewritten until after next iter's S1 -> reads are safe)
    }
}

// ============================================================================
extern "C" void kernel_launch(void* const* d_in, const int* in_sizes, int n_in,
                              void* d_out, int out_size)
{
    const float* x    = (const float*)d_in[0];   // [64,1024,512]
    const float* W    = (const float*)d_in[1];   // [512,512]
    const float* Wr   = (const float*)d_in[2];   // [512,512]
    const float* bias = (const float*)d_in[3];   // [512]
    float* out = (float*)d_out;                  // [64,512]

    void* flag_p; cudaGetSymbolAddress(&flag_p, g_flag);
    void* h_p;    cudaGetSymbolAddress(&h_p, g_h);

    // per-launch resets (graph-capturable, replay-safe)
    cudaMemsetAsync(flag_p, 0, sizeof(unsigned) * TSTEPS * NBG * NJG);
    cudaMemsetAsync(h_p, 0, sizeof(float) * BATCH * DIM);   // h_0 = 0 (buffer 0)

    rnn_fused_kernel<<<NCTA, 256>>>(W, Wr, x, bias, out);
}